// round 13
// baseline (speedup 1.0000x reference)
#include <cuda_runtime.h>
#include <cstdint>

#define NBINS   2048
#define HALF    (NBINS / 2)
#define BDIM    4          // batch (fixed for this problem)
#define RMAX    7
#define NC      36         // chunks per batch image -> grid = 4*36 = 144 CTAs
#define THREADS 1024       // ONE CTA per SM (proven phase-A optimum)

// Scratch (static device globals: allocation-free rule)
__device__ int    g_part16[BDIM * NC * RMAX * HALF];  // packed int16 pairs
__device__ int    g_merged[RMAX * BDIM * NBINS];
__device__ int    g_cnt[BDIM * NC * RMAX];
__device__ double g_pnum[RMAX * BDIM];
__device__ int    g_pden[RMAX * BDIM];
__device__ int    g_bar1 = 0;                         // grid barrier (self-reset)
__device__ int    g_bar2 = 0;                         // grid barrier (self-reset)
__device__ int    g_ticket = 0;                       // finalize ticket (self-reset)

__device__ __forceinline__ int binf(float x) {
    int k = __float2int_rz(x * (float)NBINS);
    return min(max(k, 0), NBINS - 1);
}

// Persistent fused kernel: hist -> barrier -> merge -> barrier -> scan+finalize.
// 144 CTAs at 1/SM (forced): all co-resident => spin barriers safe.
// Phase A is the R4-proven body: 4 voxels/thread, plain u32 shared atomics.
template <int RR>
__global__ void __launch_bounds__(THREADS, 1)
fused_kernel(const float* __restrict__ pred,
             const float* __restrict__ tgt,
             const int*   __restrict__ mask,  // bool serialized as int32, [R,B,V]
             float* __restrict__ outp,
             int V, int CH, int RB, int NB)
{
    extern __shared__ int sh[];               // RR * NBINS signed counters
    __shared__ int scnt[RR];
    __shared__ int wsum[33];
    __shared__ long long wacc[32];
    __shared__ int sden;

    const int t   = threadIdx.x;
    const int cid = blockIdx.x;
    const int PACKR = RR * HALF;

    // ================= Phase A: histogram (R4 body) =================
    #pragma unroll
    for (int j = t; j < RR * NBINS; j += THREADS) sh[j] = 0;
    if (t < RR) scnt[t] = 0;

    {
        const int b = cid & (BDIM - 1);
        const int c = cid >> 2;
        const size_t rstride = (size_t)BDIM * (size_t)V;

        const float* pp = pred + (size_t)b * V;
        const float* gp = tgt  + (size_t)b * V;
        const int*   mp = mask + (size_t)b * V;

        const int start = c * CH;
        const int end   = min(V, start + CH);

        int cnt[RR];
        #pragma unroll
        for (int r = 0; r < RR; r++) cnt[r] = 0;
        __syncthreads();

        for (int off = start + t * 4; off < end; off += THREADS * 4) {
            float4 pv = __ldcs(reinterpret_cast<const float4*>(pp + off));
            float4 gv = __ldcs(reinterpret_cast<const float4*>(gp + off));
            int4 mv[RR];
            #pragma unroll
            for (int r = 0; r < RR; r++)
                mv[r] = __ldcs(reinterpret_cast<const int4*>(mp + r * rstride + off));

            int p0 = binf(pv.x), p1 = binf(pv.y), p2 = binf(pv.z), p3 = binf(pv.w);
            int q0 = binf(gv.x), q1 = binf(gv.y), q2 = binf(gv.z), q3 = binf(gv.w);

            #pragma unroll
            for (int r = 0; r < RR; r++) {
                int* h = sh + r * NBINS;
                if (mv[r].x) { atomicAdd(h + p0, 1); atomicAdd(h + q0, -1); cnt[r]++; }
                if (mv[r].y) { atomicAdd(h + p1, 1); atomicAdd(h + q1, -1); cnt[r]++; }
                if (mv[r].z) { atomicAdd(h + p2, 1); atomicAdd(h + q2, -1); cnt[r]++; }
                if (mv[r].w) { atomicAdd(h + p3, 1); atomicAdd(h + q3, -1); cnt[r]++; }
            }
        }
        __syncthreads();

        // flush: pack bin pairs (per-chunk counts provably fit int16)
        int* out = g_part16 + (size_t)cid * PACKR;
        #pragma unroll
        for (int j = t; j < PACKR; j += THREADS)
            out[j] = (sh[2 * j] & 0xFFFF) | (sh[2 * j + 1] << 16);

        // per-ROI masked counts
        #pragma unroll
        for (int r = 0; r < RR; r++) {
            int v = cnt[r];
            #pragma unroll
            for (int d = 16; d; d >>= 1) v += __shfl_down_sync(0xffffffffu, v, d);
            if ((t & 31) == 0 && v) atomicAdd(&scnt[r], v);
        }
        __syncthreads();
        if (t < RR) g_cnt[cid * RR + t] = scnt[t];
    }

    // ---- grid barrier 1 ----
    __threadfence();
    __syncthreads();
    if (t == 0) {
        atomicAdd(&g_bar1, 1);
        while (*(volatile int*)&g_bar1 < NB) { }
    }
    __syncthreads();
    __threadfence();

    // ================= Phase B: merge =================
    // column idx = rb*HALF + pi; each active thread sums NC chunk partials.
    {
        const int total = RB * HALF;          // 24576 columns
        for (int idx = cid * THREADS + t; idx < total; idx += NB * THREADS) {
            int rb = idx >> 10;               // HALF == 1024
            int pi = idx & (HALF - 1);
            int r  = rb >> 2;
            int b  = rb & 3;
            const int* base = g_part16 + (size_t)b * PACKR + r * HALF + pi;
            int s0 = 0, s1 = 0;
            #pragma unroll 6
            for (int c = 0; c < NC; c++) {
                int v = base[(size_t)c * (BDIM * PACKR)];
                s0 += (int)(short)v;
                s1 += v >> 16;
            }
            *reinterpret_cast<int2*>(g_merged + (size_t)rb * NBINS + 2 * pi)
                = make_int2(s0, s1);
        }
    }

    // ---- grid barrier 2 ----
    __threadfence();
    __syncthreads();
    if (t == 0) atomicAdd(&g_bar2, 1);
    if (cid >= RB) return;                    // merge-only CTAs done
    if (t == 0) {
        while (*(volatile int*)&g_bar2 < NB) { }
    }
    __syncthreads();
    __threadfence();

    // ================= Phase C: scan (RB CTAs) + finalize =================
    {
        const int rb = cid;
        const int b  = rb & 3;
        const int r  = rb >> 2;
        const int lane = t & 31, w = t >> 5;  // 32 warps

        // thread t owns bins [2t, 2t+2)
        int2 v = *reinterpret_cast<const int2*>(g_merged + (size_t)rb * NBINS + t * 2);
        int local = v.x + v.y;

        int x = local;                        // warp inclusive scan
        #pragma unroll
        for (int d = 1; d < 32; d <<= 1) {
            int y = __shfl_up_sync(0xffffffffu, x, d);
            if (lane >= d) x += y;
        }
        if (lane == 31) wsum[w + 1] = x;
        if (t == 0) { sden = 0; wsum[0] = 0; }
        __syncthreads();
        if (t == 0)
            for (int i = 1; i < 32; i++) wsum[i + 1] += wsum[i];
        __syncthreads();

        int cum = wsum[w] + x - local;        // exclusive prefix for this thread
        int acc = 0;
        cum += v.x; acc += cum < 0 ? -cum : cum;
        cum += v.y; acc += cum < 0 ? -cum : cum;

        long long a = acc;
        #pragma unroll
        for (int d = 16; d; d >>= 1) a += __shfl_down_sync(0xffffffffu, a, d);
        if (lane == 0) wacc[w] = a;

        if (t < NC) atomicAdd(&sden, g_cnt[(t * BDIM + b) * RR + r]);
        __syncthreads();

        if (t == 0) {
            long long s = 0;
            #pragma unroll
            for (int i = 0; i < 32; i++) s += wacc[i];
            g_pnum[rb] = (double)s * (52.0 / (double)NBINS);
            g_pden[rb] = sden;
            __threadfence();

            int old = atomicAdd(&g_ticket, 1);
            if (old == RB - 1) {              // last scanner: finalize
                g_ticket = 0;                 // self-reset for graph replays
                g_bar1   = 0;
                g_bar2   = 0;
                __threadfence();
                volatile double* vn = g_pnum;
                volatile int*    vd = g_pden;
                double ls = 0.0;
                int cv = 0;
                for (int bb = 0; bb < BDIM; bb++) {
                    double num = 0.0; long long dn = 0;
                    for (int rr = 0; rr < RB / BDIM; rr++) {
                        num += vn[rr * BDIM + bb];
                        dn  += vd[rr * BDIM + bb];
                    }
                    if (dn > 0) {
                        ls += num / (double)(dn < 1 ? 1 : dn);
                        cv++;
                    }
                }
                outp[0] = (float)(ls / (double)(cv > 0 ? cv : 1));
            }
        }
    }
}

template <int RR>
static void launch_fused(const float* p, const float* g, const int* m,
                         float* o, int V, int CH, int RB)
{
    int smem = RR * NBINS * 4;                // 48 KB for RR=6; occ capped at 1
    cudaFuncSetAttribute(fused_kernel<RR>, cudaFuncAttributeMaxDynamicSharedMemorySize, smem);
    int NB = BDIM * NC;                       // 144 <= 148 SMs: all co-resident
    fused_kernel<RR><<<NB, THREADS, smem>>>(p, g, m, o, V, CH, RB, NB);
}

extern "C" void kernel_launch(void* const* d_in, const int* in_sizes, int n_in,
                              void* d_out, int out_size)
{
    const float* pred = (const float*)d_in[0];
    const float* tgt  = (const float*)d_in[1];
    const int*   mask = (const int*)d_in[2];

    int BV = in_sizes[0];                     // B*V = 4194304
    int V  = BV / BDIM;                       // 1048576
    int R  = in_sizes[2] / BV;                // 6
    int RB = R * BDIM;                        // 24
    int CH = ((V + NC - 1) / NC + 3) & ~3;    // chunk, multiple of 4

    float* o = (float*)d_out;
    switch (R) {
        case 1: launch_fused<1>(pred, tgt, mask, o, V, CH, RB); break;
        case 2: launch_fused<2>(pred, tgt, mask, o, V, CH, RB); break;
        case 3: launch_fused<3>(pred, tgt, mask, o, V, CH, RB); break;
        case 4: launch_fused<4>(pred, tgt, mask, o, V, CH, RB); break;
        case 5: launch_fused<5>(pred, tgt, mask, o, V, CH, RB); break;
        case 7: launch_fused<7>(pred, tgt, mask, o, V, CH, RB); break;
        default:
        case 6: launch_fused<6>(pred, tgt, mask, o, V, CH, RB); break;
    }
}

// round 14
// speedup vs baseline: 1.3038x; 1.3038x over previous
#include <cuda_runtime.h>
#include <cstdint>

#define SBINS   8192       // smem histogram bins (atomic-conflict optimum)
#define NBINS   2048       // flushed/output bins (tail-volume optimum)
#define HALF    (NBINS / 2)
#define BDIM    4          // batch (fixed for this problem)
#define RMAX    7
#define NC      36         // chunks per batch image -> grid = 4*36 = 144 CTAs
#define THREADS 1024       // one CTA per SM (192 KB smem forces occ 1)

// Scratch (static device globals: allocation-free rule)
__device__ int    g_part16[BDIM * NC * RMAX * HALF];  // packed int16 pairs
__device__ int    g_merged[RMAX * BDIM * NBINS];
__device__ int    g_cnt[BDIM * NC * RMAX];
__device__ double g_pnum[RMAX * BDIM];
__device__ int    g_pden[RMAX * BDIM];
__device__ int    g_bar1 = 0;                         // grid barrier (self-reset)
__device__ int    g_bar2 = 0;                         // grid barrier (self-reset)
__device__ int    g_ticket = 0;                       // finalize ticket (self-reset)

__device__ __forceinline__ int binf(float x) {
    int k = __float2int_rz(x * (float)SBINS);
    return min(max(k, 0), SBINS - 1);
}

// Persistent fused kernel: hist(8192 smem bins) -> fold-flush(2048 bins)
// -> barrier -> merge -> barrier -> scan+finalize.
// 144 CTAs at 1/SM: all co-resident => spin barriers safe.
template <int RR>
__global__ void __launch_bounds__(THREADS, 1)
fused_kernel(const float* __restrict__ pred,
             const float* __restrict__ tgt,
             const int*   __restrict__ mask,  // bool serialized as int32, [R,B,V]
             float* __restrict__ outp,
             int V, int CH, int RB, int NB)
{
    extern __shared__ int sh[];               // RR * SBINS signed counters
    __shared__ int scnt[RR];
    __shared__ int wsum[33];
    __shared__ long long wacc[32];
    __shared__ int sden;

    const int t   = threadIdx.x;
    const int cid = blockIdx.x;
    const int PACKR = RR * HALF;

    // ================= Phase A: histogram (R4 body, 8192 bins) =================
    #pragma unroll
    for (int j = t; j < RR * SBINS; j += THREADS) sh[j] = 0;
    if (t < RR) scnt[t] = 0;

    {
        const int b = cid & (BDIM - 1);
        const int c = cid >> 2;
        const size_t rstride = (size_t)BDIM * (size_t)V;

        const float* pp = pred + (size_t)b * V;
        const float* gp = tgt  + (size_t)b * V;
        const int*   mp = mask + (size_t)b * V;

        const int start = c * CH;
        const int end   = min(V, start + CH);

        int cnt[RR];
        #pragma unroll
        for (int r = 0; r < RR; r++) cnt[r] = 0;
        __syncthreads();

        for (int off = start + t * 4; off < end; off += THREADS * 4) {
            float4 pv = __ldcs(reinterpret_cast<const float4*>(pp + off));
            float4 gv = __ldcs(reinterpret_cast<const float4*>(gp + off));
            int4 mv[RR];
            #pragma unroll
            for (int r = 0; r < RR; r++)
                mv[r] = __ldcs(reinterpret_cast<const int4*>(mp + r * rstride + off));

            int p0 = binf(pv.x), p1 = binf(pv.y), p2 = binf(pv.z), p3 = binf(pv.w);
            int q0 = binf(gv.x), q1 = binf(gv.y), q2 = binf(gv.z), q3 = binf(gv.w);

            #pragma unroll
            for (int r = 0; r < RR; r++) {
                int* h = sh + r * SBINS;
                if (mv[r].x) { atomicAdd(h + p0, 1); atomicAdd(h + q0, -1); cnt[r]++; }
                if (mv[r].y) { atomicAdd(h + p1, 1); atomicAdd(h + q1, -1); cnt[r]++; }
                if (mv[r].z) { atomicAdd(h + p2, 1); atomicAdd(h + q2, -1); cnt[r]++; }
                if (mv[r].w) { atomicAdd(h + p3, 1); atomicAdd(h + q3, -1); cnt[r]++; }
            }
        }
        __syncthreads();

        // fold-flush: out bin j = sum of smem bins [4j,4j+4); pack pairs.
        // floor(x*8192)>>2 == floor(x*2048) -> results identical to NBINS=2048.
        int* out = g_part16 + (size_t)cid * PACKR;
        #pragma unroll
        for (int j = t; j < PACKR; j += THREADS) {
            int rr = j >> 10;                 // HALF == 1024
            int pi = j & (HALF - 1);
            const int* hb = sh + rr * SBINS + pi * 8;
            int d0 = hb[0] + hb[1] + hb[2] + hb[3];
            int d1 = hb[4] + hb[5] + hb[6] + hb[7];
            out[j] = (d0 & 0xFFFF) | (d1 << 16);
        }

        // per-ROI masked counts
        #pragma unroll
        for (int r = 0; r < RR; r++) {
            int v = cnt[r];
            #pragma unroll
            for (int d = 16; d; d >>= 1) v += __shfl_down_sync(0xffffffffu, v, d);
            if ((t & 31) == 0 && v) atomicAdd(&scnt[r], v);
        }
        __syncthreads();
        if (t < RR) g_cnt[cid * RR + t] = scnt[t];
    }

    // ---- grid barrier 1 ----
    __threadfence();
    __syncthreads();
    if (t == 0) {
        atomicAdd(&g_bar1, 1);
        while (*(volatile int*)&g_bar1 < NB) { }
    }
    __syncthreads();
    __threadfence();

    // ================= Phase B: merge (3.5 MB, full grid) =================
    {
        const int total = RB * HALF;          // 24576 columns
        for (int idx = cid * THREADS + t; idx < total; idx += NB * THREADS) {
            int rb = idx >> 10;               // HALF == 1024
            int pi = idx & (HALF - 1);
            int r  = rb >> 2;
            int b  = rb & 3;
            const int* base = g_part16 + (size_t)b * PACKR + r * HALF + pi;
            int s0 = 0, s1 = 0;
            #pragma unroll 6
            for (int c = 0; c < NC; c++) {
                int v = base[(size_t)c * (BDIM * PACKR)];
                s0 += (int)(short)v;
                s1 += v >> 16;
            }
            *reinterpret_cast<int2*>(g_merged + (size_t)rb * NBINS + 2 * pi)
                = make_int2(s0, s1);
        }
    }

    // ---- grid barrier 2 ----
    __threadfence();
    __syncthreads();
    if (t == 0) atomicAdd(&g_bar2, 1);
    if (cid >= RB) return;                    // merge-only CTAs done
    if (t == 0) {
        while (*(volatile int*)&g_bar2 < NB) { }
    }
    __syncthreads();
    __threadfence();

    // ================= Phase C: scan (RB CTAs) + finalize =================
    {
        const int rb = cid;
        const int b  = rb & 3;
        const int r  = rb >> 2;
        const int lane = t & 31, w = t >> 5;  // 32 warps

        // thread t owns bins [2t, 2t+2)
        int2 v = *reinterpret_cast<const int2*>(g_merged + (size_t)rb * NBINS + t * 2);
        int local = v.x + v.y;

        int x = local;                        // warp inclusive scan
        #pragma unroll
        for (int d = 1; d < 32; d <<= 1) {
            int y = __shfl_up_sync(0xffffffffu, x, d);
            if (lane >= d) x += y;
        }
        if (lane == 31) wsum[w + 1] = x;
        if (t == 0) { sden = 0; wsum[0] = 0; }
        __syncthreads();
        if (t == 0)
            for (int i = 1; i < 32; i++) wsum[i + 1] += wsum[i];
        __syncthreads();

        int cum = wsum[w] + x - local;        // exclusive prefix for this thread
        int acc = 0;
        cum += v.x; acc += cum < 0 ? -cum : cum;
        cum += v.y; acc += cum < 0 ? -cum : cum;

        long long a = acc;
        #pragma unroll
        for (int d = 16; d; d >>= 1) a += __shfl_down_sync(0xffffffffu, a, d);
        if (lane == 0) wacc[w] = a;

        if (t < NC) atomicAdd(&sden, g_cnt[(t * BDIM + b) * RR + r]);
        __syncthreads();

        if (t == 0) {
            long long s = 0;
            #pragma unroll
            for (int i = 0; i < 32; i++) s += wacc[i];
            g_pnum[rb] = (double)s * (52.0 / (double)NBINS);
            g_pden[rb] = sden;
            __threadfence();

            int old = atomicAdd(&g_ticket, 1);
            if (old == RB - 1) {              // last scanner: finalize
                g_ticket = 0;                 // self-reset for graph replays
                g_bar1   = 0;
                g_bar2   = 0;
                __threadfence();
                volatile double* vn = g_pnum;
                volatile int*    vd = g_pden;
                double ls = 0.0;
                int cv = 0;
                for (int bb = 0; bb < BDIM; bb++) {
                    double num = 0.0; long long dn = 0;
                    for (int rr = 0; rr < RB / BDIM; rr++) {
                        num += vn[rr * BDIM + bb];
                        dn  += vd[rr * BDIM + bb];
                    }
                    if (dn > 0) {
                        ls += num / (double)(dn < 1 ? 1 : dn);
                        cv++;
                    }
                }
                outp[0] = (float)(ls / (double)(cv > 0 ? cv : 1));
            }
        }
    }
}

template <int RR>
static void launch_fused(const float* p, const float* g, const int* m,
                         float* o, int V, int CH, int RB)
{
    int smem = RR * SBINS * 4;                // 192 KB for RR=6 -> occ 1
    cudaFuncSetAttribute(fused_kernel<RR>, cudaFuncAttributeMaxDynamicSharedMemorySize, smem);
    int NB = BDIM * NC;                       // 144 <= 148 SMs: all co-resident
    fused_kernel<RR><<<NB, THREADS, smem>>>(p, g, m, o, V, CH, RB, NB);
}

extern "C" void kernel_launch(void* const* d_in, const int* in_sizes, int n_in,
                              void* d_out, int out_size)
{
    const float* pred = (const float*)d_in[0];
    const float* tgt  = (const float*)d_in[1];
    const int*   mask = (const int*)d_in[2];

    int BV = in_sizes[0];                     // B*V = 4194304
    int V  = BV / BDIM;                       // 1048576
    int R  = in_sizes[2] / BV;                // 6
    int RB = R * BDIM;                        // 24
    int CH = ((V + NC - 1) / NC + 3) & ~3;    // chunk, multiple of 4

    float* o = (float*)d_out;
    switch (R) {
        case 1: launch_fused<1>(pred, tgt, mask, o, V, CH, RB); break;
        case 2: launch_fused<2>(pred, tgt, mask, o, V, CH, RB); break;
        case 3: launch_fused<3>(pred, tgt, mask, o, V, CH, RB); break;
        case 4: launch_fused<4>(pred, tgt, mask, o, V, CH, RB); break;
        case 5: launch_fused<5>(pred, tgt, mask, o, V, CH, RB); break;
        case 7: launch_fused<7>(pred, tgt, mask, o, V, CH, RB); break;
        default:
        case 6: launch_fused<6>(pred, tgt, mask, o, V, CH, RB); break;
    }
}

// round 15
// speedup vs baseline: 1.4503x; 1.1124x over previous
#include <cuda_runtime.h>
#include <cstdint>

#define SBINS   8192       // smem histogram bins (atomic-conflict optimum)
#define NBINS   2048       // flushed/output bins (tail-volume optimum)
#define HALF    (NBINS / 2)
#define BDIM    4          // batch (fixed for this problem)
#define RMAX    7
#define NC      36         // chunks per batch image -> hist grid = 4*36 = 144
#define THREADS 1024

// Scratch (static device globals: allocation-free rule)
__device__ int    g_part16[BDIM * NC * RMAX * HALF];  // packed int16 pairs
__device__ int    g_cnt[BDIM * NC * RMAX];
__device__ double g_pnum[RMAX * BDIM];
__device__ int    g_pden[RMAX * BDIM];
__device__ int    g_ticket = 0;                       // finalize ticket (self-reset)

__device__ __forceinline__ int binf(float x) {
    int k = __float2int_rz(x * (float)SBINS);
    return min(max(k, 0), SBINS - 1);
}

// One CTA: RR signed histograms (cntP - cntG) at 8192 smem bins, one chunk of
// one batch image; flush folds 4->1 into 2048 output bins. (R4-proven body.)
template <int RR>
__global__ void __launch_bounds__(THREADS, 1)
hist_kernel(const float* __restrict__ pred,
            const float* __restrict__ tgt,
            const int*   __restrict__ mask,   // bool serialized as int32, [R,B,V]
            int V, int CH)
{
    extern __shared__ int sh[];               // RR * SBINS signed counters
    __shared__ int scnt[RR];

    const int t = threadIdx.x;
    #pragma unroll
    for (int j = t; j < RR * SBINS; j += THREADS) sh[j] = 0;
    if (t < RR) scnt[t] = 0;

    const int cid = blockIdx.x;
    const int b   = cid & (BDIM - 1);
    const int c   = cid >> 2;
    const size_t rstride = (size_t)BDIM * (size_t)V;

    const float* pp = pred + (size_t)b * V;
    const float* gp = tgt  + (size_t)b * V;
    const int*   mp = mask + (size_t)b * V;

    const int start = c * CH;
    const int end   = min(V, start + CH);

    int cnt[RR];
    #pragma unroll
    for (int r = 0; r < RR; r++) cnt[r] = 0;
    __syncthreads();

    for (int off = start + t * 4; off < end; off += THREADS * 4) {
        float4 pv = __ldcs(reinterpret_cast<const float4*>(pp + off));
        float4 gv = __ldcs(reinterpret_cast<const float4*>(gp + off));
        int4 mv[RR];
        #pragma unroll
        for (int r = 0; r < RR; r++)
            mv[r] = __ldcs(reinterpret_cast<const int4*>(mp + r * rstride + off));

        int p0 = binf(pv.x), p1 = binf(pv.y), p2 = binf(pv.z), p3 = binf(pv.w);
        int q0 = binf(gv.x), q1 = binf(gv.y), q2 = binf(gv.z), q3 = binf(gv.w);

        #pragma unroll
        for (int r = 0; r < RR; r++) {
            int* h = sh + r * SBINS;
            if (mv[r].x) { atomicAdd(h + p0, 1); atomicAdd(h + q0, -1); cnt[r]++; }
            if (mv[r].y) { atomicAdd(h + p1, 1); atomicAdd(h + q1, -1); cnt[r]++; }
            if (mv[r].z) { atomicAdd(h + p2, 1); atomicAdd(h + q2, -1); cnt[r]++; }
            if (mv[r].w) { atomicAdd(h + p3, 1); atomicAdd(h + q3, -1); cnt[r]++; }
        }
    }
    __syncthreads();

    // fold-flush: output bin j = sum of smem bins [4j, 4j+4); pack pairs.
    // floor(x*8192)>>2 == floor(x*2048): identical results to NBINS=2048.
    int* out = g_part16 + (size_t)cid * (RR * HALF);
    #pragma unroll
    for (int j = t; j < RR * HALF; j += THREADS) {
        int rr = j >> 10;                     // HALF == 1024
        int pi = j & (HALF - 1);
        const int* hb = sh + rr * SBINS + pi * 8;
        int d0 = hb[0] + hb[1] + hb[2] + hb[3];
        int d1 = hb[4] + hb[5] + hb[6] + hb[7];
        out[j] = (d0 & 0xFFFF) | (d1 << 16);
    }

    // per-ROI masked counts
    #pragma unroll
    for (int r = 0; r < RR; r++) {
        int v = cnt[r];
        #pragma unroll
        for (int d = 16; d; d >>= 1) v += __shfl_down_sync(0xffffffffu, v, d);
        if ((t & 31) == 0 && v) atomicAdd(&scnt[r], v);
    }
    __syncthreads();
    if (t < RR) g_cnt[cid * RR + t] = scnt[t];
}

// Slim tail: 24 CTAs x 1024 thr. Thread t of CTA (r,b) sums packed column t
// (bins 2t, 2t+1) across NC chunks, then block prefix-scan of 2048 bins and
// sum |cum|; last-arriving CTA finalizes d_out.
__global__ void __launch_bounds__(THREADS, 1)
tail_kernel(float* __restrict__ outp, int R, int RB)
{
    __shared__ int wsum[33];
    __shared__ long long wacc[32];
    __shared__ int sden;

    const int rb = blockIdx.x;
    const int b  = rb & 3;
    const int r  = rb >> 2;
    const int t  = threadIdx.x, lane = t & 31, w = t >> 5;
    const int PACKR = R * HALF;

    // merge: packed column t of (r,b), summed over NC chunk partials
    const int* base = g_part16 + (size_t)b * PACKR + r * HALF + t;
    int s0 = 0, s1 = 0;
    #pragma unroll 6
    for (int c = 0; c < NC; c++) {
        int v = base[(size_t)c * (BDIM * PACKR)];
        s0 += (int)(short)v;
        s1 += v >> 16;
    }
    int local = s0 + s1;

    int x = local;                            // warp inclusive scan
    #pragma unroll
    for (int d = 1; d < 32; d <<= 1) {
        int y = __shfl_up_sync(0xffffffffu, x, d);
        if (lane >= d) x += y;
    }
    if (lane == 31) wsum[w + 1] = x;
    if (t == 0) { sden = 0; wsum[0] = 0; }
    __syncthreads();
    if (t == 0)
        for (int i = 1; i < 32; i++) wsum[i + 1] += wsum[i];
    __syncthreads();

    int cum = wsum[w] + x - local;            // exclusive prefix for this thread
    int acc = 0;
    cum += s0; acc += cum < 0 ? -cum : cum;
    cum += s1; acc += cum < 0 ? -cum : cum;

    long long a = acc;
    #pragma unroll
    for (int d = 16; d; d >>= 1) a += __shfl_down_sync(0xffffffffu, a, d);
    if (lane == 0) wacc[w] = a;

    if (t < NC) atomicAdd(&sden, g_cnt[(t * BDIM + b) * R + r]);
    __syncthreads();

    if (t == 0) {
        long long s = 0;
        #pragma unroll
        for (int i = 0; i < 32; i++) s += wacc[i];
        g_pnum[rb] = (double)s * (52.0 / (double)NBINS);
        g_pden[rb] = sden;
        __threadfence();

        int old = atomicAdd(&g_ticket, 1);
        if (old == RB - 1) {                  // last CTA: finalize
            g_ticket = 0;                     // self-reset for graph replays
            __threadfence();
            volatile double* vn = g_pnum;
            volatile int*    vd = g_pden;
            double ls = 0.0;
            int cv = 0;
            for (int bb = 0; bb < BDIM; bb++) {
                double num = 0.0; long long dn = 0;
                for (int rr = 0; rr < RB / BDIM; rr++) {
                    num += vn[rr * BDIM + bb];
                    dn  += vd[rr * BDIM + bb];
                }
                if (dn > 0) {
                    ls += num / (double)(dn < 1 ? 1 : dn);
                    cv++;
                }
            }
            outp[0] = (float)(ls / (double)(cv > 0 ? cv : 1));
        }
    }
}

template <int RR>
static void launch_hist(const float* p, const float* g, const int* m, int V, int CH)
{
    int smem = RR * SBINS * 4;                // 192 KB for RR=6 -> occ 1
    cudaFuncSetAttribute(hist_kernel<RR>, cudaFuncAttributeMaxDynamicSharedMemorySize, smem);
    hist_kernel<RR><<<BDIM * NC, THREADS, smem>>>(p, g, m, V, CH);
}

extern "C" void kernel_launch(void* const* d_in, const int* in_sizes, int n_in,
                              void* d_out, int out_size)
{
    const float* pred = (const float*)d_in[0];
    const float* tgt  = (const float*)d_in[1];
    const int*   mask = (const int*)d_in[2];

    int BV = in_sizes[0];                     // B*V = 4194304
    int V  = BV / BDIM;                       // 1048576
    int R  = in_sizes[2] / BV;                // 6
    int RB = R * BDIM;                        // 24
    int CH = ((V + NC - 1) / NC + 3) & ~3;    // chunk, multiple of 4

    switch (R) {
        case 1: launch_hist<1>(pred, tgt, mask, V, CH); break;
        case 2: launch_hist<2>(pred, tgt, mask, V, CH); break;
        case 3: launch_hist<3>(pred, tgt, mask, V, CH); break;
        case 4: launch_hist<4>(pred, tgt, mask, V, CH); break;
        case 5: launch_hist<5>(pred, tgt, mask, V, CH); break;
        case 7: launch_hist<7>(pred, tgt, mask, V, CH); break;
        default:
        case 6: launch_hist<6>(pred, tgt, mask, V, CH); break;
    }
    tail_kernel<<<RB, THREADS>>>((float*)d_out, R, RB);
}

// round 16
// speedup vs baseline: 1.5232x; 1.0503x over previous
#include <cuda_runtime.h>
#include <cstdint>

#define SBINS   8192       // smem histogram bins (atomic-conflict optimum)
#define NBINS   2048       // merged/output bins (4-fold of SBINS)
#define HALF    (NBINS / 2)
#define BDIM    4          // batch (fixed for this problem)
#define RMAX    7
#define NC      36         // chunks per batch image -> hist grid = 4*36 = 144
#define THREADS 1024

// Scratch (static device globals: allocation-free rule; zero-initialized at load)
__device__ int    g_merged[RMAX * BDIM * NBINS];      // RED-merged histograms
__device__ int    g_cnt[BDIM * NC * RMAX];
__device__ double g_pnum[RMAX * BDIM];
__device__ int    g_pden[RMAX * BDIM];
__device__ int    g_ticket = 0;                       // finalize ticket (self-reset)

__device__ __forceinline__ int binf(float x) {
    int k = __float2int_rz(x * (float)SBINS);
    return min(max(k, 0), SBINS - 1);
}

// One CTA: RR signed histograms (cntP - cntG) at 8192 smem bins, one chunk of
// one batch image; flush folds 4->1 and RED-merges into g_merged directly.
template <int RR>
__global__ void __launch_bounds__(THREADS, 1)
hist_kernel(const float* __restrict__ pred,
            const float* __restrict__ tgt,
            const int*   __restrict__ mask,   // bool serialized as int32, [R,B,V]
            int V, int CH)
{
    extern __shared__ int sh[];               // RR * SBINS signed counters
    __shared__ int scnt[RR];

    const int t = threadIdx.x;
    #pragma unroll
    for (int j = t; j < RR * SBINS; j += THREADS) sh[j] = 0;
    if (t < RR) scnt[t] = 0;

    const int cid = blockIdx.x;
    const int b   = cid & (BDIM - 1);
    const int c   = cid >> 2;
    const size_t rstride = (size_t)BDIM * (size_t)V;

    const float* pp = pred + (size_t)b * V;
    const float* gp = tgt  + (size_t)b * V;
    const int*   mp = mask + (size_t)b * V;

    const int start = c * CH;
    const int end   = min(V, start + CH);

    int cnt[RR];
    #pragma unroll
    for (int r = 0; r < RR; r++) cnt[r] = 0;
    __syncthreads();

    for (int off = start + t * 4; off < end; off += THREADS * 4) {
        float4 pv = __ldcs(reinterpret_cast<const float4*>(pp + off));
        float4 gv = __ldcs(reinterpret_cast<const float4*>(gp + off));
        int4 mv[RR];
        #pragma unroll
        for (int r = 0; r < RR; r++)
            mv[r] = __ldcs(reinterpret_cast<const int4*>(mp + r * rstride + off));

        int p0 = binf(pv.x), p1 = binf(pv.y), p2 = binf(pv.z), p3 = binf(pv.w);
        int q0 = binf(gv.x), q1 = binf(gv.y), q2 = binf(gv.z), q3 = binf(gv.w);

        #pragma unroll
        for (int r = 0; r < RR; r++) {
            int* h = sh + r * SBINS;
            if (mv[r].x) { atomicAdd(h + p0, 1); atomicAdd(h + q0, -1); cnt[r]++; }
            if (mv[r].y) { atomicAdd(h + p1, 1); atomicAdd(h + q1, -1); cnt[r]++; }
            if (mv[r].z) { atomicAdd(h + p2, 1); atomicAdd(h + q2, -1); cnt[r]++; }
            if (mv[r].w) { atomicAdd(h + p3, 1); atomicAdd(h + q3, -1); cnt[r]++; }
        }
    }
    __syncthreads();

    // fold-flush: merged bin j = sum of smem bins [4j, 4j+4); RED straight
    // into g_merged (no partial array). floor(x*8192)>>2 == floor(x*2048).
    #pragma unroll
    for (int j = t; j < RR * NBINS; j += THREADS) {
        int rr  = j >> 11;                    // NBINS == 2048
        int bin = j & (NBINS - 1);
        const int* hb = sh + rr * SBINS + bin * 4;
        int d = hb[0] + hb[1] + hb[2] + hb[3];
        if (d) atomicAdd(&g_merged[(size_t)(rr * BDIM + b) * NBINS + bin], d);
    }

    // per-ROI masked counts
    #pragma unroll
    for (int r = 0; r < RR; r++) {
        int v = cnt[r];
        #pragma unroll
        for (int d = 16; d; d >>= 1) v += __shfl_down_sync(0xffffffffu, v, d);
        if ((t & 31) == 0 && v) atomicAdd(&scnt[r], v);
    }
    __syncthreads();
    if (t < RR) g_cnt[cid * RR + t] = scnt[t];
}

// Slim tail: 24 CTAs x 1024 thr. Thread t owns bins (2t, 2t+1) of its (r,b):
// one int2 load, block prefix-scan, sum |cum|, then RE-ZERO its own slots
// (deterministic across graph replays). Last-arriving CTA finalizes d_out.
__global__ void __launch_bounds__(THREADS, 1)
tail_kernel(float* __restrict__ outp, int R, int RB)
{
    __shared__ int wsum[33];
    __shared__ long long wacc[32];
    __shared__ int sden;

    const int rb = blockIdx.x;
    const int b  = rb & 3;
    const int r  = rb >> 2;
    const int t  = threadIdx.x, lane = t & 31, w = t >> 5;

    int2* slot = reinterpret_cast<int2*>(g_merged + (size_t)rb * NBINS + 2 * t);
    int2 v = *slot;
    *slot = make_int2(0, 0);                  // self-reset for next replay
    int local = v.x + v.y;

    int x = local;                            // warp inclusive scan
    #pragma unroll
    for (int d = 1; d < 32; d <<= 1) {
        int y = __shfl_up_sync(0xffffffffu, x, d);
        if (lane >= d) x += y;
    }
    if (lane == 31) wsum[w + 1] = x;
    if (t == 0) { sden = 0; wsum[0] = 0; }
    __syncthreads();
    if (t == 0)
        for (int i = 1; i < 32; i++) wsum[i + 1] += wsum[i];
    __syncthreads();

    int cum = wsum[w] + x - local;            // exclusive prefix for this thread
    int acc = 0;
    cum += v.x; acc += cum < 0 ? -cum : cum;
    cum += v.y; acc += cum < 0 ? -cum : cum;

    long long a = acc;
    #pragma unroll
    for (int d = 16; d; d >>= 1) a += __shfl_down_sync(0xffffffffu, a, d);
    if (lane == 0) wacc[w] = a;

    if (t < NC) atomicAdd(&sden, g_cnt[(t * BDIM + b) * R + r]);
    __syncthreads();

    if (t == 0) {
        long long s = 0;
        #pragma unroll
        for (int i = 0; i < 32; i++) s += wacc[i];
        g_pnum[rb] = (double)s * (52.0 / (double)NBINS);
        g_pden[rb] = sden;
        __threadfence();

        int old = atomicAdd(&g_ticket, 1);
        if (old == RB - 1) {                  // last CTA: finalize
            g_ticket = 0;                     // self-reset for graph replays
            __threadfence();
            volatile double* vn = g_pnum;
            volatile int*    vd = g_pden;
            double ls = 0.0;
            int cv = 0;
            for (int bb = 0; bb < BDIM; bb++) {
                double num = 0.0; long long dn = 0;
                for (int rr = 0; rr < RB / BDIM; rr++) {
                    num += vn[rr * BDIM + bb];
                    dn  += vd[rr * BDIM + bb];
                }
                if (dn > 0) {
                    ls += num / (double)(dn < 1 ? 1 : dn);
                    cv++;
                }
            }
            outp[0] = (float)(ls / (double)(cv > 0 ? cv : 1));
        }
    }
}

template <int RR>
static void launch_hist(const float* p, const float* g, const int* m, int V, int CH)
{
    int smem = RR * SBINS * 4;                // 192 KB for RR=6 -> occ 1
    cudaFuncSetAttribute(hist_kernel<RR>, cudaFuncAttributeMaxDynamicSharedMemorySize, smem);
    hist_kernel<RR><<<BDIM * NC, THREADS, smem>>>(p, g, m, V, CH);
}

extern "C" void kernel_launch(void* const* d_in, const int* in_sizes, int n_in,
                              void* d_out, int out_size)
{
    const float* pred = (const float*)d_in[0];
    const float* tgt  = (const float*)d_in[1];
    const int*   mask = (const int*)d_in[2];

    int BV = in_sizes[0];                     // B*V = 4194304
    int V  = BV / BDIM;                       // 1048576
    int R  = in_sizes[2] / BV;                // 6
    int RB = R * BDIM;                        // 24
    int CH = ((V + NC - 1) / NC + 3) & ~3;    // chunk, multiple of 4

    switch (R) {
        case 1: launch_hist<1>(pred, tgt, mask, V, CH); break;
        case 2: launch_hist<2>(pred, tgt, mask, V, CH); break;
        case 3: launch_hist<3>(pred, tgt, mask, V, CH); break;
        case 4: launch_hist<4>(pred, tgt, mask, V, CH); break;
        case 5: launch_hist<5>(pred, tgt, mask, V, CH); break;
        case 7: launch_hist<7>(pred, tgt, mask, V, CH); break;
        default:
        case 6: launch_hist<6>(pred, tgt, mask, V, CH); break;
    }
    tail_kernel<<<RB, THREADS>>>((float*)d_out, R, RB);
}